// round 8
// baseline (speedup 1.0000x reference)
#include <cuda_runtime.h>
#include <cuda_bf16.h>
#include <cstdint>

#define LDF 68            // f32 buffer row stride (floats)
#define LDA 72            // bf16 operand row stride (elements); row = 144 B
#define XS_O 0u           // f32 residual [64][68]
#define QS_O 17408u
#define KS_O 34816u
#define VS_O 52224u
#define AH_O 69632u       // bf16 A hi [64][72]
#define AL_O 78848u
#define BH_O 88064u       // bf16 B hi [64][72]
#define BL_O 97280u
#define SMEMB 106496u
#define A2H_O 17408u      // gelu A2 aliases qs/ks scratch
#define A2L_O 26624u

__device__ uint32_t g_wblob[48 * 4608];   // per stage: 2304 hi + 2304 lo u32 ([64][72] bf16)

__device__ __forceinline__ float fast_tanh(float x) { float r; asm("tanh.approx.f32 %0, %1;" : "=f"(r) : "f"(x)); return r; }
__device__ __forceinline__ float gelu_t(float x) {
    float t = fast_tanh(0.7978845608028654f * (x + 0.044715f * x * x * x));
    return 0.5f * x * (1.0f + t);
}
__device__ __forceinline__ uint32_t pack_hl(float v0, float v1, uint32_t& lo) {
    __nv_bfloat16 h0 = __float2bfloat16(v0), h1 = __float2bfloat16(v1);
    __nv_bfloat16 l0 = __float2bfloat16(v0 - __bfloat162float(h0));
    __nv_bfloat16 l1 = __float2bfloat16(v1 - __bfloat162float(h1));
    lo = (uint32_t)__bfloat16_as_ushort(l0) | ((uint32_t)__bfloat16_as_ushort(l1) << 16);
    return (uint32_t)__bfloat16_as_ushort(h0) | ((uint32_t)__bfloat16_as_ushort(h1) << 16);
}
__device__ __forceinline__ void ldmx4(uint32_t& r0, uint32_t& r1, uint32_t& r2, uint32_t& r3, uint32_t a) {
    asm volatile("ldmatrix.sync.aligned.m8n8.x4.shared.b16 {%0,%1,%2,%3}, [%4];"
        : "=r"(r0), "=r"(r1), "=r"(r2), "=r"(r3) : "r"(a));
}
__device__ __forceinline__ void ldmx4t(uint32_t& r0, uint32_t& r1, uint32_t& r2, uint32_t& r3, uint32_t a) {
    asm volatile("ldmatrix.sync.aligned.m8n8.x4.trans.shared.b16 {%0,%1,%2,%3}, [%4];"
        : "=r"(r0), "=r"(r1), "=r"(r2), "=r"(r3) : "r"(a));
}
__device__ __forceinline__ void mma16816(float (&c)[4], uint32_t a0, uint32_t a1, uint32_t a2, uint32_t a3,
                                         uint32_t b0, uint32_t b1) {
    asm volatile("mma.sync.aligned.m16n8k16.row.col.f32.bf16.bf16.f32 "
        "{%0,%1,%2,%3}, {%4,%5,%6,%7}, {%8,%9}, {%0,%1,%2,%3};"
        : "+f"(c[0]), "+f"(c[1]), "+f"(c[2]), "+f"(c[3])
        : "r"(a0), "r"(a1), "r"(a2), "r"(a3), "r"(b0), "r"(b1));
}

// ---- weight prep: stage s = l*12 + {0:Wq,1:Wk,2:Wv,3:Wo,4..7:W1_c,8..11:W2_c} ----
__global__ void prep_weights(const float* __restrict__ Wq, const float* __restrict__ Wk,
                             const float* __restrict__ Wv, const float* __restrict__ Wo,
                             const float* __restrict__ W1, const float* __restrict__ W2) {
    int s = blockIdx.x, l = s / 12, r = s % 12;
    for (int idx = threadIdx.x; idx < 2304; idx += blockDim.x) {
        int k = idx / 36, n2 = idx % 36;
        float vv[2];
        #pragma unroll
        for (int t = 0; t < 2; t++) {
            int c = 2 * n2 + t;
            float v = 0.f;
            if (r < 3) {                       // Wq/Wk/Wv: head-padded col permute
                const float* src = (r == 0 ? Wq : (r == 1 ? Wk : Wv)) + l * 3136;
                int hd = c >> 3, di = c & 7;
                if (k < 56 && c < 64 && di < 7) v = src[k * 56 + hd * 7 + di];
            } else if (r == 3) {               // Wo: head-padded row permute
                const float* src = Wo + l * 3136;
                int hk = k >> 3, ki = k & 7;
                if (c < 56 && k < 64 && ki < 7) v = src[(hk * 7 + ki) * 56 + c];
            } else if (r < 8) {
                const float* src = W1 + l * 12544;
                if (k < 56 && c < 56) v = src[k * 224 + (r - 4) * 56 + c];
            } else {
                const float* src = W2 + l * 12544;
                if (k < 56 && c < 56) v = src[((r - 8) * 56 + k) * 56 + c];
            }
            vv[t] = v;
        }
        uint32_t lo, hi = pack_hl(vv[0], vv[1], lo);
        g_wblob[s * 4608 + idx] = hi;
        g_wblob[s * 4608 + 2304 + idx] = lo;
    }
}

// ---- register-prefetched B staging ----
struct BR { uint4 a, b, c, d, e; };
__device__ __forceinline__ void ldb(BR& br, int s, int tid) {
    const uint4* p = (const uint4*)(g_wblob + s * 4608);
    br.a = __ldg(p + tid);       br.b = __ldg(p + tid + 256);
    br.c = __ldg(p + tid + 512); br.d = __ldg(p + tid + 768);
    if (tid < 128) br.e = __ldg(p + tid + 1024);
}
__device__ __forceinline__ void stb(char* sm, const BR& br, int tid) {
    uint4* d = (uint4*)(sm + BH_O);
    d[tid] = br.a; d[tid + 256] = br.b; d[tid + 512] = br.c; d[tid + 768] = br.d;
    if (tid < 128) d[tid + 1024] = br.e;
}

// ---- GEMM D[64][64] = A[64][64] @ B[64][64] via mma.sync, bf16x3 split, fused epilogue ----
// warp -> mt = warp>>1 (16 rows), nh = warp&1 (32 cols). MODE: 0 store->Dbuf, 1 Dbuf+=, 2 gelu(+bias)->A2
template <int MODE>
__device__ __forceinline__ void gemm_m(char* sm, uint32_t smb, uint32_t ahO, uint32_t alO,
                                       float* __restrict__ Dbuf, const float* __restrict__ bias, int tid) {
    const int lane = tid & 31, warp = tid >> 5;
    const int mt = warp >> 1, nh = warp & 1;
    float c[4][4];
    #pragma unroll
    for (int j = 0; j < 4; j++) { c[j][0] = c[j][1] = c[j][2] = c[j][3] = 0.f; }

    uint32_t aoff = ((uint32_t)(mt * 16 + (lane & 15)) * LDA + 8 * (lane >> 4)) * 2;
    uint32_t ahA = smb + ahO + aoff, alA = smb + alO + aoff;
    int bg = lane >> 3, bi = lane & 7;
    uint32_t boff0 = ((uint32_t)((bg & 1) * 8 + bi) * LDA + nh * 32 + (bg >> 1) * 8) * 2;
    uint32_t bhA = smb + BH_O + boff0, blA = smb + BL_O + boff0;

    #pragma unroll
    for (int ks = 0; ks < 4; ks++) {
        uint32_t kb = ks * 32;              // A: +16 cols
        uint32_t kr = ks * (16 * LDA * 2);  // B: +16 rows
        uint32_t a0, a1, a2, a3, l0, l1, l2, l3;
        ldmx4 (a0, a1, a2, a3, ahA + kb);
        ldmx4 (l0, l1, l2, l3, alA + kb);
        uint32_t bh[8], bl[8];
        ldmx4t(bh[0], bh[1], bh[2], bh[3], bhA + kr);
        ldmx4t(bh[4], bh[5], bh[6], bh[7], bhA + kr + 32);
        ldmx4t(bl[0], bl[1], bl[2], bl[3], blA + kr);
        ldmx4t(bl[4], bl[5], bl[6], bl[7], blA + kr + 32);
        #pragma unroll
        for (int j = 0; j < 4; j++) {
            mma16816(c[j], a0, a1, a2, a3, bh[2 * j], bh[2 * j + 1]);
            mma16816(c[j], a0, a1, a2, a3, bl[2 * j], bl[2 * j + 1]);
            mma16816(c[j], l0, l1, l2, l3, bh[2 * j], bh[2 * j + 1]);
        }
    }

    const int r0 = mt * 16 + (lane >> 2);
    const int cq = (lane & 3) * 2;
    #pragma unroll
    for (int j = 0; j < 4; j++) {
        int col = nh * 32 + j * 8 + cq;
        if (MODE == 0) {
            *(float2*)(Dbuf + r0 * LDF + col)       = make_float2(c[j][0], c[j][1]);
            *(float2*)(Dbuf + (r0 + 8) * LDF + col) = make_float2(c[j][2], c[j][3]);
        } else if (MODE == 1) {
            float2 p0 = *(float2*)(Dbuf + r0 * LDF + col);
            float2 p1 = *(float2*)(Dbuf + (r0 + 8) * LDF + col);
            p0.x += c[j][0]; p0.y += c[j][1]; p1.x += c[j][2]; p1.y += c[j][3];
            *(float2*)(Dbuf + r0 * LDF + col)       = p0;
            *(float2*)(Dbuf + (r0 + 8) * LDF + col) = p1;
        } else {
            uint32_t h0 = 0, lo0 = 0, h1 = 0, lo1 = 0;
            if (!(nh == 1 && j == 3)) {          // cols 56..63: zero pads, no bias OOB
                float b0 = __ldg(bias + col), b1 = __ldg(bias + col + 1);
                h0 = pack_hl(gelu_t(c[j][0] + b0), gelu_t(c[j][1] + b1), lo0);
                h1 = pack_hl(gelu_t(c[j][2] + b0), gelu_t(c[j][3] + b1), lo1);
            }
            uint32_t o0 = ((uint32_t)(r0 * LDA + col)) * 2, o1 = ((uint32_t)((r0 + 8) * LDA + col)) * 2;
            *(uint32_t*)(sm + A2H_O + o0) = h0;  *(uint32_t*)(sm + A2L_O + o0) = lo0;
            *(uint32_t*)(sm + A2H_O + o1) = h1;  *(uint32_t*)(sm + A2L_O + o1) = lo1;
        }
    }
}

// ---- LN of x -> A bf16 hi/lo; 4 threads/row; optional x += b2 (stats from pre-b2 x) ----
template <bool ADDB>
__device__ __forceinline__ void row_cvt_ln(float* __restrict__ xs, const float* __restrict__ g,
                                           const float* __restrict__ b, const float* __restrict__ b2,
                                           char* sm, int tid) {
    int r = tid >> 2, part = tid & 3;
    float* xr = xs + r * LDF + part * 14;
    float v[14];
    #pragma unroll
    for (int j = 0; j < 7; j++) *(float2*)(v + 2 * j) = *(const float2*)(xr + 2 * j);
    float s = 0.f, ss = 0.f;
    #pragma unroll
    for (int j = 0; j < 14; j++) { s += v[j]; ss += v[j] * v[j]; }
    s  += __shfl_xor_sync(0xffffffffu, s, 1);
    ss += __shfl_xor_sync(0xffffffffu, ss, 1);
    s  += __shfl_xor_sync(0xffffffffu, s, 2);
    ss += __shfl_xor_sync(0xffffffffu, ss, 2);
    if (ADDB) {
        #pragma unroll
        for (int j = 0; j < 14; j++) xr[j] = v[j] + __ldg(b2 + part * 14 + j);
    }
    float m = s * (1.f / 56.f), rs = rsqrtf(ss * (1.f / 56.f) - m * m + 1e-5f);
    uint32_t* ah = (uint32_t*)(sm + AH_O + ((uint32_t)(r * LDA + part * 14)) * 2);
    uint32_t* al = (uint32_t*)(sm + AL_O + ((uint32_t)(r * LDA + part * 14)) * 2);
    #pragma unroll
    for (int t = 0; t < 7; t++) {
        int cl = part * 14 + 2 * t;
        float v0 = (v[2 * t]     - m) * rs * __ldg(g + cl)     + __ldg(b + cl);
        float v1 = (v[2 * t + 1] - m) * rs * __ldg(g + cl + 1) + __ldg(b + cl + 1);
        uint32_t lo, hi = pack_hl(v0, v1, lo);
        ah[t] = hi; al[t] = lo;
    }
}

__global__ void __launch_bounds__(256, 2)
nbody_tc(const float* __restrict__ nodes, const float* __restrict__ edges,
         const float* __restrict__ mask,
         const float* __restrict__ W_in, const float* __restrict__ b_in,
         const float* __restrict__ W_gp, const float* __restrict__ b_gp,
         const float* __restrict__ ln1g, const float* __restrict__ ln1b,
         const float* __restrict__ ln2g, const float* __restrict__ ln2b,
         const float* __restrict__ b1, const float* __restrict__ b2,
         float* __restrict__ out, int Btot) {
    extern __shared__ char sm[];
    const int tid = threadIdx.x, bx = blockIdx.x;
    const uint32_t smb = (uint32_t)__cvta_generic_to_shared(sm);
    float* xs = (float*)(sm + XS_O);
    float* qs = (float*)(sm + QS_O);
    float* ks = (float*)(sm + KS_O);
    float* vs = (float*)(sm + VS_O);
    BR br;
    ldb(br, 0, tid);            // prefetch Wq(l=0)

    // zero residual; zero A K-pad cols 56..63 (hi+lo) against NaN garbage
    #pragma unroll 1
    for (int i = tid; i < 64 * LDF / 4; i += 256) ((float4*)xs)[i] = make_float4(0.f, 0.f, 0.f, 0.f);
    if (tid < 128) {
        int buf = tid >> 6, r = tid & 63;
        *(uint4*)(sm + AH_O + (uint32_t)buf * (AL_O - AH_O) + ((uint32_t)(r * LDA + 56)) * 2) = make_uint4(0u, 0u, 0u, 0u);
    }

    // ---- embedding ----
    if (tid < 50) {
        int g = tid / 25, s = tid % 25;
        long Bi = (long)bx * 2 + g;
        if (Bi < Btot) {
            const float* sp = (s < 5) ? nodes + (Bi * 5 + s) * 24 : edges + (Bi * 20 + (s - 5)) * 24;
            float xin[24];
            #pragma unroll
            for (int i = 0; i < 24; i++) xin[i] = __ldg(sp + i);
            const int GR[8] = {0, 1, 1, 1, 2, 2, 2, 3};
            const int POS[8] = {0, 1, 2, 4, 3, 5, 6, 7};
            float* xrow = xs + (g * 32 + s) * LDF;
            #pragma unroll 1
            for (int n = 0; n < 7; n++) {
                float acc[8];
                #pragma unroll
                for (int i = 0; i < 8; i++) acc[i] = (i == 0) ? __ldg(b_gp + n) : 0.f;
                #pragma unroll 1
                for (int m = 0; m < 7; m++) {
                    float mv[8];
                    #pragma unroll
                    for (int i = 0; i < 8; i++) {
                        int gr = GR[i];
                        mv[i] = xin[i] * __ldg(W_in + m * 12 + gr) + xin[8 + i] * __ldg(W_in + m * 12 + 4 + gr)
                              + xin[16 + i] * __ldg(W_in + m * 12 + 8 + gr);
                    }
                    mv[0] += __ldg(b_in + m);
                    float gp[8];
                    #pragma unroll
                    for (int j = 0; j < 8; j++) gp[j] = 0.f;
                    #pragma unroll
                    for (int a = 0; a < 8; a++)
                        #pragma unroll
                        for (int bb = 0; bb < 8; bb++) {
                            int sc = 0;
                            #pragma unroll
                            for (int t = a >> 1; t; t >>= 1) sc += __popc(t & bb);
                            gp[POS[a ^ bb]] += ((sc & 1) ? -1.f : 1.f) * mv[POS[a]] * mv[POS[bb]];
                        }
                    #pragma unroll
                    for (int i = 0; i < 8; i++) {
                        int gr = GR[i];
                        acc[i] += mv[i] * __ldg(W_gp + n * 56 + m * 4 + gr)
                                + gp[i] * __ldg(W_gp + n * 56 + (m + 7) * 4 + gr);
                    }
                }
                #pragma unroll
                for (int i = 0; i < 8; i++) xrow[n * 8 + i] = acc[i];
            }
        }
    }
    __syncthreads();
    stb(sm, br, tid);   // B <- Wq(l=0)
    __syncthreads();

    #pragma unroll 1
    for (int l = 0; l < 4; l++) {
        const int sbase = l * 12;
        row_cvt_ln<false>(xs, ln1g + l * 56, ln1b + l * 56, nullptr, sm, tid);
        __syncthreads();

        ldb(br, sbase + 1, tid);
        gemm_m<0>(sm, smb, AH_O, AL_O, qs, nullptr, tid);
        __syncthreads(); stb(sm, br, tid); __syncthreads();
        ldb(br, sbase + 2, tid);
        gemm_m<0>(sm, smb, AH_O, AL_O, ks, nullptr, tid);
        __syncthreads(); stb(sm, br, tid); __syncthreads();
        ldb(br, sbase + 3, tid);
        gemm_m<0>(sm, smb, AH_O, AL_O, vs, nullptr, tid);
        __syncthreads(); stb(sm, br, tid); __syncthreads();

        // attention: o packed straight into bf16 A operand (hi/lo)
        #pragma unroll 1
        for (int it = tid; it < 400; it += 256) {
            int g = it / 200, r = it % 200, hh = r / 25, s = r % 25;
            long Bi = (long)bx * 2 + g;
            int rq = (g * 32 + s) * LDF + hh * 8;
            float4 q0 = *(const float4*)(qs + rq), q1 = *(const float4*)(qs + rq + 4);
            const float* mrow = mask + (Bi * 25 + s) * 25;
            float sc[25]; float mx = -1e30f;
            #pragma unroll
            for (int ki = 0; ki < 25; ki++) {
                const float* kp = ks + (g * 32 + ki) * LDF + hh * 8;
                float4 k0 = *(const float4*)(kp), k1 = *(const float4*)(kp + 4);
                float dot = q0.x * k0.x + q0.y * k0.y + q0.z * k0.z + q0.w * k0.w
                          + q1.x * k1.x + q1.y * k1.y + q1.z * k1.z + q1.w * k1.w;
                float msk = (Bi < Btot) ? __ldg(mrow + ki) : 0.f;
                sc[ki] = dot * 0.3779644730092272f + msk;
                mx = fmaxf(mx, sc[ki]);
            }
            float sum = 0.f;
            #pragma unroll
            for (int ki = 0; ki < 25; ki++) { float e = __expf(sc[ki] - mx); sc[ki] = e; sum += e; }
            float inv = 1.f / sum;
            float4 o0 = make_float4(0.f, 0.f, 0.f, 0.f), o1 = o0;
            #pragma unroll
            for (int ki = 0; ki < 25; ki++) {
                const float* vp = vs + (g * 32 + ki) * LDF + hh * 8;
                float4 v0 = *(const float4*)(vp), v1 = *(const float4*)(vp + 4);
                float p = sc[ki];
                o0.x += p * v0.x; o0.y += p * v0.y; o0.z += p * v0.z; o0.w += p * v0.w;
                o1.x += p * v1.x; o1.y += p * v1.y; o1.z += p * v1.z; o1.w += p * v1.w;
            }
            uint32_t ob = ((uint32_t)((g * 32 + s) * LDA + hh * 8)) * 2;
            uint32_t lo, hi;
            hi = pack_hl(o0.x * inv, o0.y * inv, lo);
            *(uint32_t*)(sm + AH_O + ob)      = hi; *(uint32_t*)(sm + AL_O + ob)      = lo;
            hi = pack_hl(o0.z * inv, o0.w * inv, lo);
            *(uint32_t*)(sm + AH_O + ob + 4)  = hi; *(uint32_t*)(sm + AL_O + ob + 4)  = lo;
            hi = pack_hl(o1.x * inv, o1.y * inv, lo);
            *(uint32_t*)(sm + AH_O + ob + 8)  = hi; *(uint32_t*)(sm + AL_O + ob + 8)  = lo;
            hi = pack_hl(o1.z * inv, o1.w * inv, lo);
            *(uint32_t*)(sm + AH_O + ob + 12) = hi; *(uint32_t*)(sm + AL_O + ob + 12) = lo;
        }
        __syncthreads();

        ldb(br, sbase + 4, tid);
        gemm_m<1>(sm, smb, AH_O, AL_O, xs, nullptr, tid);   // x += o @ Wo
        __syncthreads(); stb(sm, br, tid); __syncthreads(); // B <- W1_0

        row_cvt_ln<true>(xs, ln2g + l * 56, ln2b + l * 56, b2 + l * 56, sm, tid);
        __syncthreads();

        #pragma unroll 1
        for (int c = 0; c < 4; c++) {
            ldb(br, sbase + 8 + c, tid);
            gemm_m<2>(sm, smb, AH_O, AL_O, nullptr, b1 + l * 224 + c * 56, tid);   // gelu -> A2
            __syncthreads(); stb(sm, br, tid); __syncthreads();                    // B <- W2_c
            int nxt = (c < 3) ? (sbase + 5 + c) : ((l < 3) ? (sbase + 12) : 0);
            ldb(br, nxt, tid);
            gemm_m<1>(sm, smb, A2H_O, A2L_O, xs, nullptr, tid);                    // x += gelu @ W2_c
            __syncthreads(); stb(sm, br, tid); __syncthreads();
        }
    }

    // ---- output: rows s<5 per batch, D cols 8..15 ----
    if (tid < 80) {
        int g = tid / 40, r = tid % 40, s = r / 8, i = r % 8;
        long Bi = (long)bx * 2 + g;
        if (Bi < Btot) out[(Bi * 5 + s) * 8 + i] = xs[(g * 32 + s) * LDF + 8 + i];
    }
}

extern "C" void kernel_launch(void* const* d_in, const int* in_sizes, int n_in,
                              void* d_out, int out_size) {
    int o = (n_in >= 20) ? 4 : 3;
    const float* nodes = (const float*)d_in[0];
    const float* edges = (const float*)d_in[1];
    const float* mask  = (const float*)d_in[2];
    const float* W_in  = (const float*)d_in[o + 0];
    const float* b_in  = (const float*)d_in[o + 1];
    const float* W_gp  = (const float*)d_in[o + 2];
    const float* b_gp  = (const float*)d_in[o + 3];
    const float* Wq    = (const float*)d_in[o + 4];
    const float* Wk    = (const float*)d_in[o + 5];
    const float* Wv    = (const float*)d_in[o + 6];
    const float* Wo    = (const float*)d_in[o + 7];
    const float* ln1g  = (const float*)d_in[o + 8];
    const float* ln1b  = (const float*)d_in[o + 9];
    const float* ln2g  = (const float*)d_in[o + 10];
    const float* ln2b  = (const float*)d_in[o + 11];
    const float* W1    = (const float*)d_in[o + 12];
    const float* b1    = (const float*)d_in[o + 13];
    const float* W2    = (const float*)d_in[o + 14];
    const float* b2    = (const float*)d_in[o + 15];

    int B = in_sizes[0] / 120;
    prep_weights<<<48, 256>>>(Wq, Wk, Wv, Wo, W1, W2);
    cudaFuncSetAttribute(nbody_tc, cudaFuncAttributeMaxDynamicSharedMemorySize, SMEMB);
    nbody_tc<<<(B + 1) / 2, 256, SMEMB>>>(nodes, edges, mask, W_in, b_in, W_gp, b_gp,
                                          ln1g, ln1b, ln2g, ln2b, b1, b2, (float*)d_out, B);
}